// round 1
// baseline (speedup 1.0000x reference)
#include <cuda_runtime.h>

#define N_NODES 50000
#define N_EDGES 800000
#define ET (N_EDGES + N_NODES)
#define F_IN 256
#define H 250
#define P 256   // padded pitch for feature rows

// ---------------- scratch (static device globals; no allocation) ------------
__device__ float g_h1[(size_t)N_NODES * P];
__device__ float g_x1[(size_t)N_NODES * P];
__device__ float g_hs[(size_t)N_NODES * P];
__device__ float g_hd[(size_t)N_NODES * P];
__device__ float g_as[N_NODES];
__device__ float g_ad[N_NODES];
__device__ int   g_deg[N_NODES];
__device__ int   g_rowptr[N_NODES + 1];
__device__ int   g_cursor[N_NODES];
__device__ int   g_col[ET];

// ---------------- CSR build -------------------------------------------------
__global__ void k_init_deg() {
    int i = blockIdx.x * blockDim.x + threadIdx.x;
    if (i < N_NODES) g_deg[i] = 1;   // self loop
}

__global__ void k_count(const int* __restrict__ dst) {
    int i = blockIdx.x * blockDim.x + threadIdx.x;
    if (i < N_EDGES) atomicAdd(&g_deg[dst[i]], 1);
}

// single-block exclusive scan over g_deg -> g_rowptr / g_cursor
__global__ void k_scan() {
    __shared__ int sh[1024];
    __shared__ int off;
    int tid = threadIdx.x;
    if (tid == 0) off = 0;
    for (int base = 0; base < N_NODES; base += 1024) {
        int i = base + tid;
        int v = (i < N_NODES) ? g_deg[i] : 0;
        sh[tid] = v;
        __syncthreads();
        #pragma unroll
        for (int d = 1; d < 1024; d <<= 1) {
            int t = (tid >= d) ? sh[tid - d] : 0;
            __syncthreads();
            sh[tid] += t;
            __syncthreads();
        }
        int excl = off + sh[tid] - v;
        if (i < N_NODES) { g_rowptr[i] = excl; g_cursor[i] = excl; }
        int tot = sh[1023];
        __syncthreads();
        if (tid == 0) off += tot;
        __syncthreads();
    }
    if (threadIdx.x == 0) g_rowptr[N_NODES] = off;
}

__global__ void k_fill(const int* __restrict__ src, const int* __restrict__ dst) {
    int i = blockIdx.x * blockDim.x + threadIdx.x;
    if (i < N_EDGES) {
        int pos = atomicAdd(&g_cursor[dst[i]], 1);
        g_col[pos] = src[i];
    } else if (i < ET) {
        int v = i - N_EDGES;
        int pos = atomicAdd(&g_cursor[v], 1);
        g_col[pos] = v;
    }
}

// ---------------- SGEMM: C[M,Nc] = A[M,K] @ B[K,Nc] -------------------------
// A pitch = P (256), B pitch = H (250, packed weight), C pitch = P.
// MODE: 0 -> A = external x, C = g_h1
//       1 -> A = g_x1,       C = g_hs
//       2 -> A = g_x1,       C = g_hd
template<int MODE>
__global__ __launch_bounds__(256)
void sgemm(const float* __restrict__ Aext, const float* __restrict__ B,
           int M, int Nc, int K) {
    const float* A = (MODE == 0) ? Aext : g_x1;
    float* C = (MODE == 0) ? g_h1 : (MODE == 1 ? g_hs : g_hd);

    __shared__ float As[8][132];   // transposed A tile [k][m], padded
    __shared__ float Bs[8][132];   // B tile [k][n], padded

    int bm = blockIdx.y * 128;
    int bn = blockIdx.x * 128;
    int tid = threadIdx.x;           // 256 threads
    int tx = tid & 15;               // 0..15 -> n micro
    int ty = tid >> 4;               // 0..15 -> m micro

    float acc[8][8];
    #pragma unroll
    for (int i = 0; i < 8; i++)
        #pragma unroll
        for (int j = 0; j < 8; j++) acc[i][j] = 0.f;

    for (int kt = 0; kt < K; kt += 8) {
        // load A tile: 128 rows x 8 k
        #pragma unroll
        for (int l = 0; l < 4; l++) {
            int idx = tid + l * 256;       // 0..1023
            int m = idx >> 3;              // 0..127
            int k = idx & 7;
            int gr = bm + m, gk = kt + k;
            float v = 0.f;
            if (gr < M && gk < K) v = A[(size_t)gr * P + gk];
            As[k][m] = v;
        }
        // load B tile: 8 k x 128 n
        #pragma unroll
        for (int l = 0; l < 4; l++) {
            int idx = tid + l * 256;
            int k = idx >> 7;              // 0..7
            int n = idx & 127;
            int gk = kt + k, gn = bn + n;
            float v = 0.f;
            if (gk < K && gn < Nc) v = B[(size_t)gk * H + gn];
            Bs[k][n] = v;
        }
        __syncthreads();

        #pragma unroll
        for (int k = 0; k < 8; k++) {
            float a[8], b[8];
            float4 a0 = *(const float4*)&As[k][ty * 8];
            float4 a1 = *(const float4*)&As[k][ty * 8 + 4];
            float4 b0 = *(const float4*)&Bs[k][tx * 8];
            float4 b1 = *(const float4*)&Bs[k][tx * 8 + 4];
            a[0]=a0.x; a[1]=a0.y; a[2]=a0.z; a[3]=a0.w;
            a[4]=a1.x; a[5]=a1.y; a[6]=a1.z; a[7]=a1.w;
            b[0]=b0.x; b[1]=b0.y; b[2]=b0.z; b[3]=b0.w;
            b[4]=b1.x; b[5]=b1.y; b[6]=b1.z; b[7]=b1.w;
            #pragma unroll
            for (int i = 0; i < 8; i++)
                #pragma unroll
                for (int j = 0; j < 8; j++)
                    acc[i][j] += a[i] * b[j];
        }
        __syncthreads();
    }

    #pragma unroll
    for (int i = 0; i < 8; i++) {
        int gr = bm + ty * 8 + i;
        if (gr >= M) continue;
        #pragma unroll
        for (int j = 0; j < 8; j++) {
            int gn = bn + tx * 8 + j;
            if (gn < Nc) C[(size_t)gr * P + gn] = acc[i][j];
        }
    }
}

// ---------------- per-node attention dot ------------------------------------
// SRC: 0=g_h1, 1=g_hs, 2=g_hd ; DSTSEL: 0=g_as, 1=g_ad
template<int SRC, int DSTSEL>
__global__ void k_dot(const float* __restrict__ a) {
    const float* h = (SRC == 0) ? g_h1 : (SRC == 1 ? g_hs : g_hd);
    float* o = (DSTSEL == 0) ? g_as : g_ad;
    int gw = (blockIdx.x * blockDim.x + threadIdx.x) >> 5;
    int lane = threadIdx.x & 31;
    if (gw >= N_NODES) return;
    const float* row = h + (size_t)gw * P;
    float s = 0.f;
    for (int k = lane; k < H; k += 32) s += row[k] * a[k];
    #pragma unroll
    for (int d = 16; d; d >>= 1) s += __shfl_xor_sync(0xffffffffu, s, d);
    if (lane == 0) o[gw] = s;
}

// ---------------- warp-per-node softmax aggregation -------------------------
// SRC: 0 -> h_src = g_h1, out = g_x1 (pitch P, relu)
//      1 -> h_src = g_hs, out = external (pitch H, no relu)
template<int SRC, bool RELU>
__global__ void k_agg(const float* __restrict__ bias, float* __restrict__ oext,
                      int op) {
    const float* hsrc = (SRC == 0) ? g_h1 : g_hs;
    float* out = (SRC == 0) ? g_x1 : oext;
    int gw = (blockIdx.x * blockDim.x + threadIdx.x) >> 5;
    int lane = threadIdx.x & 31;
    if (gw >= N_NODES) return;

    int start = g_rowptr[gw], end = g_rowptr[gw + 1];
    float adv = g_ad[gw];

    // pass 1: max over as[src] (lrelu monotone -> fold after max)
    float mx = -1e30f;
    for (int j = start + lane; j < end; j += 32)
        mx = fmaxf(mx, g_as[g_col[j]]);
    #pragma unroll
    for (int d = 16; d; d >>= 1) mx = fmaxf(mx, __shfl_xor_sync(0xffffffffu, mx, d));
    float t = mx + adv;
    float m = (t > 0.f) ? t : 0.2f * t;

    // pass 2: weighted feature sum (all lanes walk edges together)
    float acc[8];
    #pragma unroll
    for (int k = 0; k < 8; k++) acc[k] = 0.f;
    float denom = 0.f;
    for (int j = start; j < end; j++) {
        int s = g_col[j];
        float e0 = g_as[s] + adv;
        float e = (e0 > 0.f) ? e0 : 0.2f * e0;
        float w = __expf(e - m);
        denom += w;
        const float* row = hsrc + (size_t)s * P;
        #pragma unroll
        for (int k = 0; k < 8; k++) {
            int f = k * 32 + lane;
            if (f < H) acc[k] += w * row[f];
        }
    }
    float inv = 1.0f / denom;
    #pragma unroll
    for (int k = 0; k < 8; k++) {
        int f = k * 32 + lane;
        if (f < H) {
            float v = acc[k] * inv + bias[f];
            if (RELU) v = fmaxf(v, 0.f);
            out[(size_t)gw * op + f] = v;
        }
    }
}

// ---------------- launch ----------------------------------------------------
extern "C" void kernel_launch(void* const* d_in, const int* in_sizes, int n_in,
                              void* d_out, int out_size) {
    const float* x   = (const float*)d_in[0];
    const int*   ei  = (const int*)d_in[1];
    const float* W1  = (const float*)d_in[2];
    const float* as1 = (const float*)d_in[3];
    const float* ad1 = (const float*)d_in[4];
    const float* b1  = (const float*)d_in[5];
    const float* W2s = (const float*)d_in[6];
    const float* W2d = (const float*)d_in[7];
    const float* as2 = (const float*)d_in[8];
    const float* ad2 = (const float*)d_in[9];
    const float* b2  = (const float*)d_in[10];
    float* out = (float*)d_out;

    const int* src = ei;
    const int* dst = ei + N_EDGES;

    // CSR build
    k_init_deg<<<(N_NODES + 255) / 256, 256>>>();
    k_count<<<(N_EDGES + 255) / 256, 256>>>(dst);
    k_scan<<<1, 1024>>>();
    k_fill<<<(ET + 255) / 256, 256>>>(src, dst);

    dim3 gg((H + 127) / 128, (N_NODES + 127) / 128);

    // layer 1
    sgemm<0><<<gg, 256>>>(x, W1, N_NODES, H, F_IN);
    int warpsGrid = (N_NODES * 32 + 255) / 256;
    k_dot<0, 0><<<warpsGrid, 256>>>(as1);
    k_dot<0, 1><<<warpsGrid, 256>>>(ad1);
    k_agg<0, true><<<warpsGrid, 256>>>(b1, nullptr, P);

    // layer 2
    sgemm<1><<<gg, 256>>>(nullptr, W2s, N_NODES, H, H);
    sgemm<2><<<gg, 256>>>(nullptr, W2d, N_NODES, H, H);
    k_dot<1, 0><<<warpsGrid, 256>>>(as2);
    k_dot<2, 1><<<warpsGrid, 256>>>(ad2);
    k_agg<1, false><<<warpsGrid, 256>>>(b2, out, H);
}

// round 2
// speedup vs baseline: 1.8407x; 1.8407x over previous
#include <cuda_runtime.h>

#define N_NODES 50000
#define N_EDGES 800000
#define ET (N_EDGES + N_NODES)
#define F_IN 256
#define H 250
#define P 256   // padded pitch

// ---------------- scratch (device globals; no allocation) -------------------
__device__ __align__(16) float g_h1[(size_t)N_NODES * P];
__device__ __align__(16) float g_x1[(size_t)N_NODES * P];
__device__ __align__(16) float g_hs[(size_t)N_NODES * P];
__device__ __align__(16) float g_W1p[256 * 256];
__device__ __align__(16) float g_W2p[256 * 256];
__device__ __align__(16) float g_cv[4][256];   // composite attention vectors
__device__ float g_as[N_NODES];
__device__ float g_ad[N_NODES];
__device__ int   g_deg[N_NODES];
__device__ int   g_rowptr[N_NODES + 1];
__device__ int   g_cursor[N_NODES];
__device__ int   g_col[ET];
__device__ int   g_part[64];

// ---------------- CSR build -------------------------------------------------
__global__ void k_init_deg() {
    int i = blockIdx.x * blockDim.x + threadIdx.x;
    if (i < N_NODES) g_deg[i] = 1;   // self loop
}

__global__ void k_count(const int* __restrict__ dst) {
    int i = blockIdx.x * blockDim.x + threadIdx.x;
    if (i < N_EDGES) atomicAdd(&g_deg[dst[i]], 1);
}

__global__ void k_blockscan() {
    __shared__ int sh[1024];
    int t = threadIdx.x, b = blockIdx.x;
    int i = b * 1024 + t;
    int v = (i < N_NODES) ? g_deg[i] : 0;
    sh[t] = v;
    __syncthreads();
    #pragma unroll
    for (int d = 1; d < 1024; d <<= 1) {
        int tv = (t >= d) ? sh[t - d] : 0;
        __syncthreads();
        sh[t] += tv;
        __syncthreads();
    }
    if (i < N_NODES) g_rowptr[i] = sh[t] - v;   // local exclusive
    if (t == 1023) g_part[b] = sh[1023];
}

__global__ void k_partscan(int nb) {
    if (threadIdx.x == 0) {
        int acc = 0;
        for (int b = 0; b < nb; b++) { int v = g_part[b]; g_part[b] = acc; acc += v; }
    }
}

__global__ void k_addoff() {
    int i = blockIdx.x * blockDim.x + threadIdx.x;
    if (i < N_NODES) {
        int r = g_rowptr[i] + g_part[i >> 10];
        g_rowptr[i] = r;
        g_cursor[i] = r;
    }
    if (i == 0) g_rowptr[N_NODES] = ET;
}

__global__ void k_fill(const int* __restrict__ src, const int* __restrict__ dst) {
    int i = blockIdx.x * blockDim.x + threadIdx.x;
    if (i < N_EDGES) {
        int pos = atomicAdd(&g_cursor[dst[i]], 1);
        g_col[pos] = src[i];
    } else if (i < ET) {
        int v = i - N_EDGES;
        int pos = atomicAdd(&g_cursor[v], 1);
        g_col[pos] = v;
    }
}

// ---------------- weight pad + composite vectors ----------------------------
__global__ void k_padW(const float* __restrict__ W1, const float* __restrict__ W2s) {
    int i = blockIdx.x * blockDim.x + threadIdx.x;   // 65536
    int r = i >> 8, c = i & 255;
    g_W1p[i] = (c < H) ? W1[r * H + c] : 0.f;
    g_W2p[i] = (r < H && c < H) ? W2s[r * H + c] : 0.f;
}

__global__ void k_cvec(const float* __restrict__ W1,
                       const float* __restrict__ as1, const float* __restrict__ ad1,
                       const float* __restrict__ W2s, const float* __restrict__ W2d,
                       const float* __restrict__ as2, const float* __restrict__ ad2) {
    int t = blockIdx.x * blockDim.x + threadIdx.x;   // 1024
    int vec = t >> 8, k = t & 255;
    float s = 0.f;
    if (vec == 0) {
        for (int h = 0; h < H; h++) s += W1[k * H + h] * as1[h];
    } else if (vec == 1) {
        for (int h = 0; h < H; h++) s += W1[k * H + h] * ad1[h];
    } else if (vec == 2) {
        if (k < H) for (int h = 0; h < H; h++) s += W2s[k * H + h] * as2[h];
    } else {
        if (k < H) for (int h = 0; h < H; h++) s += W2d[k * H + h] * ad2[h];
    }
    g_cv[vec][k] = s;
}

// ---------------- SGEMM: C[M,256] = A[M,256] @ Bp[256,256], double buffered --
// MODE 0: A=x (ext), B=g_W1p, C=g_h1 ; MODE 1: A=g_x1, B=g_W2p, C=g_hs
template<int MODE>
__global__ __launch_bounds__(256)
void sgemm(const float* __restrict__ Aext, int M) {
    const float* A = (MODE == 0) ? Aext : g_x1;
    const float* B = (MODE == 0) ? g_W1p : g_W2p;
    float* C = (MODE == 0) ? g_h1 : g_hs;

    __shared__ float As[2][8][128];
    __shared__ float Bs[2][8][128];

    int tid = threadIdx.x;
    int bm = blockIdx.y * 128, bn = blockIdx.x * 128;
    int arow = tid >> 1, akq = (tid & 1) * 4;
    int brow = tid >> 5, bcol = (tid & 31) * 4;
    int tx = tid & 15, ty = tid >> 4;

    int aM = min(bm + arow, M - 1);
    const float* Aptr = A + (size_t)aM * P + akq;
    const float* Bptr = B + brow * 256 + bn + bcol;

    float acc[8][8];
    #pragma unroll
    for (int i = 0; i < 8; i++)
        #pragma unroll
        for (int j = 0; j < 8; j++) acc[i][j] = 0.f;

    float4 ra = *(const float4*)(Aptr);
    float4 rb = *(const float4*)(Bptr);
    As[0][akq + 0][arow] = ra.x; As[0][akq + 1][arow] = ra.y;
    As[0][akq + 2][arow] = ra.z; As[0][akq + 3][arow] = ra.w;
    *(float4*)&Bs[0][brow][bcol] = rb;
    __syncthreads();

    int buf = 0;
    for (int kt = 8; kt <= 256; kt += 8) {
        if (kt < 256) {
            ra = *(const float4*)(Aptr + kt);
            rb = *(const float4*)(Bptr + (size_t)kt * 256);
        }
        #pragma unroll
        for (int k = 0; k < 8; k++) {
            float a[8], b[8];
            *(float4*)(a)     = *(const float4*)&As[buf][k][ty * 8];
            *(float4*)(a + 4) = *(const float4*)&As[buf][k][ty * 8 + 4];
            *(float4*)(b)     = *(const float4*)&Bs[buf][k][tx * 8];
            *(float4*)(b + 4) = *(const float4*)&Bs[buf][k][tx * 8 + 4];
            #pragma unroll
            for (int i = 0; i < 8; i++)
                #pragma unroll
                for (int j = 0; j < 8; j++)
                    acc[i][j] += a[i] * b[j];
        }
        if (kt < 256) {
            buf ^= 1;
            As[buf][akq + 0][arow] = ra.x; As[buf][akq + 1][arow] = ra.y;
            As[buf][akq + 2][arow] = ra.z; As[buf][akq + 3][arow] = ra.w;
            *(float4*)&Bs[buf][brow][bcol] = rb;
            __syncthreads();
        }
    }

    #pragma unroll
    for (int i = 0; i < 8; i++) {
        int gr = bm + ty * 8 + i;
        if (gr >= M) continue;
        float* cp = C + (size_t)gr * P + bn + tx * 8;
        *(float4*)(cp)     = make_float4(acc[i][0], acc[i][1], acc[i][2], acc[i][3]);
        *(float4*)(cp + 4) = make_float4(acc[i][4], acc[i][5], acc[i][6], acc[i][7]);
    }
}

// ---------------- fused dual GEMV: as[i]=x[i]·c1, ad[i]=x[i]·c2 --------------
// L=0: rows from ext x, vectors g_cv[0],g_cv[1]; L=1: rows g_x1, g_cv[2],g_cv[3]
template<int L>
__global__ void k_gemv2(const float* __restrict__ xin) {
    const float* X = (L == 0) ? xin : g_x1;
    const float* c1 = g_cv[L == 0 ? 0 : 2];
    const float* c2 = g_cv[L == 0 ? 1 : 3];
    int gw = (blockIdx.x * blockDim.x + threadIdx.x) >> 5;
    int lane = threadIdx.x & 31;
    if (gw >= N_NODES) return;
    const float* row = X + (size_t)gw * P;
    float s1 = 0.f, s2 = 0.f;
    #pragma unroll
    for (int k = 0; k < 8; k++) {
        int f = k * 32 + lane;
        float v = row[f];
        s1 += v * c1[f];
        s2 += v * c2[f];
    }
    #pragma unroll
    for (int d = 16; d; d >>= 1) {
        s1 += __shfl_xor_sync(0xffffffffu, s1, d);
        s2 += __shfl_xor_sync(0xffffffffu, s2, d);
    }
    if (lane == 0) { g_as[gw] = s1; g_ad[gw] = s2; }
}

// ---------------- warp-per-node softmax aggregation -------------------------
// SRC 0: feats g_h1 -> out g_x1 (pitch P, relu). SRC 1: feats g_hs -> ext (pitch H)
template<int SRC, bool RELU>
__global__ void k_agg(const float* __restrict__ bias, float* __restrict__ oext,
                      int op) {
    const float* hsrc = (SRC == 0) ? g_h1 : g_hs;
    float* out = (SRC == 0) ? g_x1 : oext;
    int gw = (blockIdx.x * blockDim.x + threadIdx.x) >> 5;
    int lane = threadIdx.x & 31;
    if (gw >= N_NODES) return;

    int start = g_rowptr[gw], end = g_rowptr[gw + 1];
    float adv = g_ad[gw];

    // pass 1: max over as[src]; leaky_relu is monotone -> fold after max
    float mx = -1e30f;
    for (int j = start + lane; j < end; j += 32)
        mx = fmaxf(mx, g_as[g_col[j]]);
    #pragma unroll
    for (int d = 16; d; d >>= 1) mx = fmaxf(mx, __shfl_xor_sync(0xffffffffu, mx, d));
    float t = mx + adv;
    float m = (t > 0.f) ? t : 0.2f * t;

    // pass 2: weighted feature sum
    float acc[8];
    #pragma unroll
    for (int k = 0; k < 8; k++) acc[k] = 0.f;
    float denom = 0.f;
    for (int j = start; j < end; j++) {
        int s = g_col[j];
        float e0 = g_as[s] + adv;
        float e = (e0 > 0.f) ? e0 : 0.2f * e0;
        float w = __expf(e - m);
        denom += w;
        const float* row = hsrc + (size_t)s * P;
        #pragma unroll
        for (int k = 0; k < 8; k++) {
            int f = k * 32 + lane;
            if (f < H) acc[k] += w * row[f];
        }
    }
    float inv = 1.0f / denom;
    #pragma unroll
    for (int k = 0; k < 8; k++) {
        int f = k * 32 + lane;
        if (f < H) {
            float v = acc[k] * inv + bias[f];
            if (RELU) v = fmaxf(v, 0.f);
            out[(size_t)gw * op + f] = v;
        }
    }
}

// ---------------- launch ----------------------------------------------------
extern "C" void kernel_launch(void* const* d_in, const int* in_sizes, int n_in,
                              void* d_out, int out_size) {
    const float* x   = (const float*)d_in[0];
    const int*   ei  = (const int*)d_in[1];
    const float* W1  = (const float*)d_in[2];
    const float* as1 = (const float*)d_in[3];
    const float* ad1 = (const float*)d_in[4];
    const float* b1  = (const float*)d_in[5];
    const float* W2s = (const float*)d_in[6];
    const float* W2d = (const float*)d_in[7];
    const float* as2 = (const float*)d_in[8];
    const float* ad2 = (const float*)d_in[9];
    const float* b2  = (const float*)d_in[10];
    float* out = (float*)d_out;

    const int* src = ei;
    const int* dst = ei + N_EDGES;

    int nb = (N_NODES + 1023) / 1024;   // 49

    // CSR build
    k_init_deg<<<(N_NODES + 255) / 256, 256>>>();
    k_count<<<(N_EDGES + 255) / 256, 256>>>(dst);
    k_blockscan<<<nb, 1024>>>();
    k_partscan<<<1, 32>>>(nb);
    k_addoff<<<(N_NODES + 255) / 256, 256>>>();
    k_fill<<<(ET + 255) / 256, 256>>>(src, dst);

    // weight prep
    k_padW<<<256, 256>>>(W1, W2s);
    k_cvec<<<4, 256>>>(W1, as1, ad1, W2s, W2d, as2, ad2);

    dim3 gg(2, (N_NODES + 127) / 128);
    int warpsGrid = (N_NODES * 32 + 255) / 256;

    // layer 1
    sgemm<0><<<gg, 256>>>(x, N_NODES);
    k_gemv2<0><<<warpsGrid, 256>>>(x);
    k_agg<0, true><<<warpsGrid, 256>>>(b1, nullptr, P);

    // layer 2 (h_d GEMM eliminated: folded into composite GEMV)
    sgemm<1><<<gg, 256>>>(nullptr, N_NODES);
    k_gemv2<1><<<warpsGrid, 256>>>(nullptr);
    k_agg<1, false><<<warpsGrid, 256>>>(b2, out, H);
}

// round 8
// speedup vs baseline: 2.3332x; 1.2675x over previous
#include <cuda_runtime.h>
#include <cuda_bf16.h>
#include <mma.h>

using namespace nvcuda;

#define N_NODES 50000
#define N_EDGES 800000
#define ET (N_EDGES + N_NODES)
#define H 250
#define P 256
#define SM_TOTAL 75776

// ---------------- scratch (device globals; no allocation) -------------------
__device__ __align__(16) float g_h1[(size_t)N_NODES * P];
__device__ __align__(16) float g_x1[(size_t)N_NODES * P];
__device__ __align__(16) float g_hs[(size_t)N_NODES * P];
__device__ __align__(16) float g_W1p[256 * 256];
__device__ __align__(16) float g_W2p[256 * 256];
__device__ __align__(16) float g_cv[4][256];
__device__ float g_as[N_NODES], g_ad[N_NODES];
__device__ float g_as2[N_NODES], g_ad2[N_NODES];
__device__ int g_deg[N_NODES], g_rowptr[N_NODES + 1], g_cursor[N_NODES];
__device__ int g_col[ET];
__device__ int g_part[64];

// ---------------- CSR build -------------------------------------------------
__global__ void k_init_deg() {
    int i = blockIdx.x * blockDim.x + threadIdx.x;
    if (i < N_NODES) g_deg[i] = 1;
}
__global__ void k_count(const int* __restrict__ dst) {
    int i = blockIdx.x * blockDim.x + threadIdx.x;
    if (i < N_EDGES) atomicAdd(&g_deg[dst[i]], 1);
}
__global__ void k_blockscan() {
    __shared__ int sh[1024];
    int t = threadIdx.x, b = blockIdx.x;
    int i = b * 1024 + t;
    int v = (i < N_NODES) ? g_deg[i] : 0;
    sh[t] = v;
    __syncthreads();
    #pragma unroll
    for (int d = 1; d < 1024; d <<= 1) {
        int tv = (t >= d) ? sh[t - d] : 0;
        __syncthreads();
        sh[t] += tv;
        __syncthreads();
    }
    if (i < N_NODES) g_rowptr[i] = sh[t] - v;
    if (t == 1023) g_part[b] = sh[1023];
}
__global__ void k_partscan(int nb) {
    if (threadIdx.x == 0) {
        int acc = 0;
        for (int b = 0; b < nb; b++) { int v = g_part[b]; g_part[b] = acc; acc += v; }
    }
}
__global__ void k_addoff() {
    int i = blockIdx.x * blockDim.x + threadIdx.x;
    if (i < N_NODES) {
        int r = g_rowptr[i] + g_part[i >> 10];
        g_rowptr[i] = r;
        g_cursor[i] = r;
    }
    if (i == 0) g_rowptr[N_NODES] = ET;
}
__global__ void k_fill(const int* __restrict__ src, const int* __restrict__ dst) {
    int i = blockIdx.x * blockDim.x + threadIdx.x;
    if (i < N_EDGES) {
        int pos = atomicAdd(&g_cursor[dst[i]], 1);
        g_col[pos] = src[i];
    } else if (i < ET) {
        int v = i - N_EDGES;
        int pos = atomicAdd(&g_cursor[v], 1);
        g_col[pos] = v;
    }
}

// ---------------- weight pad + composite vectors ----------------------------
__global__ void k_padW(const float* __restrict__ W1, const float* __restrict__ W2s) {
    int i = blockIdx.x * blockDim.x + threadIdx.x;
    int r = i >> 8, c = i & 255;
    g_W1p[i] = (c < H) ? W1[r * H + c] : 0.f;
    g_W2p[i] = (r < H && c < H) ? W2s[r * H + c] : 0.f;
}

__global__ void k_cvec(const float* __restrict__ W1,
                       const float* __restrict__ as1, const float* __restrict__ ad1,
                       const float* __restrict__ W2s, const float* __restrict__ W2d,
                       const float* __restrict__ as2, const float* __restrict__ ad2) {
    int t = blockIdx.x * blockDim.x + threadIdx.x;
    int vec = t >> 8, k = t & 255;
    float s = 0.f;
    if (vec == 0)      { for (int h = 0; h < H; h++) s += W1[k * H + h] * as1[h]; }
    else if (vec == 1) { for (int h = 0; h < H; h++) s += W1[k * H + h] * ad1[h]; }
    else if (vec == 2) { if (k < H) for (int h = 0; h < H; h++) s += W2s[k * H + h] * as2[h]; }
    else               { if (k < H) for (int h = 0; h < H; h++) s += W2d[k * H + h] * ad2[h]; }
    g_cv[vec][k] = s;
}

// ---------------- layer-1 dual GEMV -----------------------------------------
__global__ void k_gemv2_x(const float* __restrict__ xin) {
    int gw = (blockIdx.x * blockDim.x + threadIdx.x) >> 5;
    int lane = threadIdx.x & 31;
    if (gw >= N_NODES) return;
    const float* row = xin + (size_t)gw * P;
    float s1 = 0.f, s2 = 0.f;
    #pragma unroll
    for (int k = 0; k < 8; k++) {
        int f = k * 32 + lane;
        float v = row[f];
        s1 += v * g_cv[0][f];
        s2 += v * g_cv[1][f];
    }
    #pragma unroll
    for (int d = 16; d; d >>= 1) {
        s1 += __shfl_xor_sync(0xffffffffu, s1, d);
        s2 += __shfl_xor_sync(0xffffffffu, s2, d);
    }
    if (lane == 0) { g_as[gw] = s1; g_ad[gw] = s2; }
}

// ---------------- WMMA bf16 3-pass GEMM: C[M,256] = A[M,256] @ B[256,256] ---
// MODE 0: A = x (ext), B = g_W1p, C = g_h1
// MODE 1: A = g_x1,    B = g_W2p, C = g_hs
template<int MODE>
__global__ __launch_bounds__(256, 1)
void gemm_wmma(const float* __restrict__ Aext, int M) {
    const float* A = MODE ? g_x1 : Aext;
    const float* B = MODE ? g_W2p : g_W1p;
    float* C = MODE ? g_hs : g_h1;

    extern __shared__ __align__(16) unsigned char smraw[];
    __nv_bfloat16* sAh = (__nv_bfloat16*)smraw;
    __nv_bfloat16* sAl = sAh + 10240;
    __nv_bfloat16* sBh = sAh + 20480;
    __nv_bfloat16* sBl = sAh + 29184;

    int tid = threadIdx.x, wid = tid >> 5, lane = tid & 31;
    int bm = blockIdx.y * 128, bn = blockIdx.x * 128;
    int wr = (wid >> 1) * 32, wc = (wid & 1) * 64;

    wmma::fragment<wmma::accumulator, 16, 16, 16, float> acc[2][4];
    #pragma unroll
    for (int i = 0; i < 2; i++)
        #pragma unroll
        for (int j = 0; j < 4; j++) wmma::fill_fragment(acc[i][j], 0.f);

    float4 pa[4], pb[4];
    #pragma unroll
    for (int l = 0; l < 4; l++) {
        int q = tid + l * 256;
        int row = q >> 3, c4 = q & 7;
        int gr = bm + row; if (gr > M - 1) gr = M - 1;
        pa[l] = *(const float4*)(A + (size_t)gr * P + c4 * 4);
        int brow = q >> 5, bc4 = q & 31;
        pb[l] = *(const float4*)(B + (size_t)brow * 256 + bn + bc4 * 4);
    }
    #pragma unroll
    for (int l = 0; l < 4; l++) {
        int q = tid + l * 256;
        int row = q >> 3, c4 = q & 7;
        float va[4] = {pa[l].x, pa[l].y, pa[l].z, pa[l].w};
        #pragma unroll
        for (int e = 0; e < 4; e++) {
            __nv_bfloat16 hb = __float2bfloat16(va[e]);
            sAh[row * 40 + c4 * 4 + e] = hb;
            sAl[row * 40 + c4 * 4 + e] = __float2bfloat16(va[e] - __bfloat162float(hb));
        }
        int brow = q >> 5, bc4 = q & 31;
        float vb[4] = {pb[l].x, pb[l].y, pb[l].z, pb[l].w};
        #pragma unroll
        for (int e = 0; e < 4; e++) {
            __nv_bfloat16 hb = __float2bfloat16(vb[e]);
            sBh[brow * 136 + bc4 * 4 + e] = hb;
            sBl[brow * 136 + bc4 * 4 + e] = __float2bfloat16(vb[e] - __bfloat162float(hb));
        }
    }
    __syncthreads();

    for (int it = 0; it < 8; it++) {
        int buf = it & 1;
        int nbuf = buf ^ 1;
        if (it < 7) {
            int kt = (it + 1) * 32;
            #pragma unroll
            for (int l = 0; l < 4; l++) {
                int q = tid + l * 256;
                int row = q >> 3, c4 = q & 7;
                int gr = bm + row; if (gr > M - 1) gr = M - 1;
                pa[l] = *(const float4*)(A + (size_t)gr * P + kt + c4 * 4);
                int brow = q >> 5, bc4 = q & 31;
                pb[l] = *(const float4*)(B + (size_t)(kt + brow) * 256 + bn + bc4 * 4);
            }
        }
        wmma::fragment<wmma::matrix_a, 16, 16, 16, __nv_bfloat16, wmma::row_major> fah[2], fal[2];
        wmma::fragment<wmma::matrix_b, 16, 16, 16, __nv_bfloat16, wmma::row_major> fbh, fbl;
        #pragma unroll
        for (int ks = 0; ks < 2; ks++) {
            int ko = ks * 16;
            #pragma unroll
            for (int i = 0; i < 2; i++) {
                wmma::load_matrix_sync(fah[i], sAh + buf * 5120 + (wr + i * 16) * 40 + ko, 40);
                wmma::load_matrix_sync(fal[i], sAl + buf * 5120 + (wr + i * 16) * 40 + ko, 40);
            }
            #pragma unroll
            for (int j = 0; j < 4; j++) {
                wmma::load_matrix_sync(fbh, sBh + buf * 4352 + ko * 136 + wc + j * 16, 136);
                wmma::load_matrix_sync(fbl, sBl + buf * 4352 + ko * 136 + wc + j * 16, 136);
                #pragma unroll
                for (int i = 0; i < 2; i++) {
                    wmma::mma_sync(acc[i][j], fah[i], fbh, acc[i][j]);
                    wmma::mma_sync(acc[i][j], fal[i], fbh, acc[i][j]);
                    wmma::mma_sync(acc[i][j], fah[i], fbl, acc[i][j]);
                }
            }
        }
        if (it < 7) {
            #pragma unroll
            for (int l = 0; l < 4; l++) {
                int q = tid + l * 256;
                int row = q >> 3, c4 = q & 7;
                float va[4] = {pa[l].x, pa[l].y, pa[l].z, pa[l].w};
                #pragma unroll
                for (int e = 0; e < 4; e++) {
                    __nv_bfloat16 hb = __float2bfloat16(va[e]);
                    sAh[nbuf * 5120 + row * 40 + c4 * 4 + e] = hb;
                    sAl[nbuf * 5120 + row * 40 + c4 * 4 + e] =
                        __float2bfloat16(va[e] - __bfloat162float(hb));
                }
                int brow = q >> 5, bc4 = q & 31;
                float vb[4] = {pb[l].x, pb[l].y, pb[l].z, pb[l].w};
                #pragma unroll
                for (int e = 0; e < 4; e++) {
                    __nv_bfloat16 hb = __float2bfloat16(vb[e]);
                    sBh[nbuf * 4352 + brow * 136 + bc4 * 4 + e] = hb;
                    sBl[nbuf * 4352 + brow * 136 + bc4 * 4 + e] =
                        __float2bfloat16(vb[e] - __bfloat162float(hb));
                }
            }
            __syncthreads();
        }
    }

    // epilogue
    if (bm + 128 <= M) {
        #pragma unroll
        for (int i = 0; i < 2; i++)
            #pragma unroll
            for (int j = 0; j < 4; j++)
                wmma::store_matrix_sync(C + (size_t)(bm + wr + i * 16) * 256 + bn + wc + j * 16,
                                        acc[i][j], 256, wmma::mem_row_major);
    } else {
        __syncthreads();
        // ldm 20 (multiple of 4) — ldm 17 was UB and corrupted the last tile
        float* stage = (float*)smraw + wid * 320;
        #pragma unroll
        for (int i = 0; i < 2; i++) {
            #pragma unroll
            for (int j = 0; j < 4; j++) {
                wmma::store_matrix_sync(stage, acc[i][j], 20, wmma::mem_row_major);
                __syncwarp();
                for (int e = lane; e < 256; e += 32) {
                    int r = e >> 4, c = e & 15;
                    int gr = bm + wr + i * 16 + r;
                    if (gr < M) C[(size_t)gr * 256 + bn + wc + j * 16 + c] = stage[r * 20 + c];
                }
                __syncwarp();
            }
        }
    }
}

// ---------------- warp-per-node softmax aggregation -------------------------
template<int SRC, bool RELU>
__global__ void k_agg(const float* __restrict__ bias, float* __restrict__ oext,
                      int op) {
    const float* hsrc = (SRC == 0) ? g_h1 : g_hs;
    const float* asv = (SRC == 0) ? g_as : g_as2;
    const float* adva = (SRC == 0) ? g_ad : g_ad2;
    float* out = (SRC == 0) ? g_x1 : oext;
    int gw = (blockIdx.x * blockDim.x + threadIdx.x) >> 5;
    int lane = threadIdx.x & 31;
    if (gw >= N_NODES) return;

    int start = g_rowptr[gw], end = g_rowptr[gw + 1];
    float adv = adva[gw];

    float mx = -1e30f;
    for (int j = start + lane; j < end; j += 32)
        mx = fmaxf(mx, asv[g_col[j]]);
    #pragma unroll
    for (int d = 16; d; d >>= 1) mx = fmaxf(mx, __shfl_xor_sync(0xffffffffu, mx, d));
    float t = mx + adv;
    float m = (t > 0.f) ? t : 0.2f * t;

    float acc[8];
    #pragma unroll
    for (int k = 0; k < 8; k++) acc[k] = 0.f;
    float denom = 0.f;
    for (int j = start; j < end; j++) {
        int s = g_col[j];
        float e0 = asv[s] + adv;
        float e = (e0 > 0.f) ? e0 : 0.2f * e0;
        float w = __expf(e - m);
        denom += w;
        const float* row = hsrc + (size_t)s * P;
        #pragma unroll
        for (int k = 0; k < 8; k++) {
            int f = k * 32 + lane;
            if (f < H) acc[k] += w * row[f];
        }
    }
    float inv = 1.0f / denom;
    float s1 = 0.f, s2 = 0.f;
    #pragma unroll
    for (int k = 0; k < 8; k++) {
        int f = k * 32 + lane;
        if (f < H) {
            float v = acc[k] * inv + bias[f];
            if (RELU) v = fmaxf(v, 0.f);
            out[(size_t)gw * op + f] = v;
            if (SRC == 0) { s1 += v * g_cv[2][f]; s2 += v * g_cv[3][f]; }
        }
    }
    if (SRC == 0) {
        #pragma unroll
        for (int d = 16; d; d >>= 1) {
            s1 += __shfl_xor_sync(0xffffffffu, s1, d);
            s2 += __shfl_xor_sync(0xffffffffu, s2, d);
        }
        if (lane == 0) { g_as2[gw] = s1; g_ad2[gw] = s2; }
    }
}

// ---------------- launch ----------------------------------------------------
extern "C" void kernel_launch(void* const* d_in, const int* in_sizes, int n_in,
                              void* d_out, int out_size) {
    const float* x   = (const float*)d_in[0];
    const int*   ei  = (const int*)d_in[1];
    const float* W1  = (const float*)d_in[2];
    const float* as1 = (const float*)d_in[3];
    const float* ad1 = (const float*)d_in[4];
    const float* b1  = (const float*)d_in[5];
    const float* W2s = (const float*)d_in[6];
    const float* W2d = (const float*)d_in[7];
    const float* as2 = (const float*)d_in[8];
    const float* ad2 = (const float*)d_in[9];
    const float* b2  = (const float*)d_in[10];
    float* out = (float*)d_out;

    const int* src = ei;
    const int* dst = ei + N_EDGES;

    cudaFuncSetAttribute(gemm_wmma<0>, cudaFuncAttributeMaxDynamicSharedMemorySize, SM_TOTAL);
    cudaFuncSetAttribute(gemm_wmma<1>, cudaFuncAttributeMaxDynamicSharedMemorySize, SM_TOTAL);

    int nb = (N_NODES + 1023) / 1024;

    k_init_deg<<<(N_NODES + 255) / 256, 256>>>();
    k_count<<<(N_EDGES + 255) / 256, 256>>>(dst);
    k_blockscan<<<nb, 1024>>>();
    k_partscan<<<1, 32>>>(nb);
    k_addoff<<<(N_NODES + 255) / 256, 256>>>();
    k_fill<<<(ET + 255) / 256, 256>>>(src, dst);

    k_padW<<<256, 256>>>(W1, W2s);
    k_cvec<<<4, 256>>>(W1, as1, ad1, W2s, W2d, as2, ad2);

    dim3 gg(2, (N_NODES + 127) / 128);
    int warpsGrid = (N_NODES * 32 + 255) / 256;

    // layer 1
    gemm_wmma<0><<<gg, 256, SM_TOTAL>>>(x, N_NODES);
    k_gemv2_x<<<warpsGrid, 256>>>(x);
    k_agg<0, true><<<warpsGrid, 256>>>(b1, nullptr, P);

    // layer 2 (W2_dst GEMM folded into composite vector; dots fused in k_agg<0>)
    gemm_wmma<1><<<gg, 256, SM_TOTAL>>>(nullptr, N_NODES);
    k_agg<1, false><<<warpsGrid, 256>>>(b2, out, H);
}

// round 10
// speedup vs baseline: 2.7394x; 1.1741x over previous
#include <cuda_runtime.h>
#include <cuda_bf16.h>
#include <mma.h>

using namespace nvcuda;

#define N_NODES 50000
#define N_EDGES 800000
#define ET (N_EDGES + N_NODES)
#define H 250
#define P 256
#define NTILES 391
#define NPAD (NTILES * 128)
#define SM_TOTAL 108544

// ---------------- scratch (device globals; zero-initialized at load) --------
__device__ __align__(16) float g_h1[(size_t)NPAD * P];
__device__ __align__(16) float g_hs[(size_t)NPAD * P];
__device__ __align__(16) __nv_bfloat16 g_xh[(size_t)NPAD * P];
__device__ __align__(16) __nv_bfloat16 g_xl[(size_t)NPAD * P];
__device__ __align__(16) __nv_bfloat16 g_x1h[(size_t)NPAD * P];
__device__ __align__(16) __nv_bfloat16 g_x1l[(size_t)NPAD * P];
__device__ __align__(16) __nv_bfloat16 g_W1h[256 * 256], g_W1l[256 * 256];
__device__ __align__(16) __nv_bfloat16 g_W2h[256 * 256], g_W2l[256 * 256];
__device__ __align__(16) float g_cv[4][256];
__device__ float g_as[N_NODES], g_ad[N_NODES];
__device__ float g_as2[N_NODES], g_ad2[N_NODES];
__device__ int g_deg[N_NODES], g_rowptr[N_NODES + 1], g_cursor[N_NODES];
__device__ int g_col[ET];
__device__ int g_part[64];

// ---------------- CSR build -------------------------------------------------
__global__ void k_init_deg() {
    int i = blockIdx.x * blockDim.x + threadIdx.x;
    if (i < N_NODES) g_deg[i] = 1;
}
__global__ void k_count(const int* __restrict__ dst) {
    int i = blockIdx.x * blockDim.x + threadIdx.x;
    if (i < N_EDGES) atomicAdd(&g_deg[dst[i]], 1);
}
__global__ void k_blockscan() {
    __shared__ int sh[1024];
    int t = threadIdx.x, b = blockIdx.x;
    int i = b * 1024 + t;
    int v = (i < N_NODES) ? g_deg[i] : 0;
    sh[t] = v;
    __syncthreads();
    #pragma unroll
    for (int d = 1; d < 1024; d <<= 1) {
        int tv = (t >= d) ? sh[t - d] : 0;
        __syncthreads();
        sh[t] += tv;
        __syncthreads();
    }
    if (i < N_NODES) g_rowptr[i] = sh[t] - v;
    if (t == 1023) g_part[b] = sh[1023];
}
__global__ void k_partscan(int nb) {
    __shared__ int sh[64];
    int t = threadIdx.x;
    int v = (t < nb) ? g_part[t] : 0;
    sh[t] = v;
    __syncthreads();
    #pragma unroll
    for (int d = 1; d < 64; d <<= 1) {
        int tv = (t >= d) ? sh[t - d] : 0;
        __syncthreads();
        sh[t] += tv;
        __syncthreads();
    }
    if (t < nb) g_part[t] = sh[t] - v;   // exclusive
}
__global__ void k_addoff() {
    int i = blockIdx.x * blockDim.x + threadIdx.x;
    if (i < N_NODES) {
        int r = g_rowptr[i] + g_part[i >> 10];
        g_rowptr[i] = r;
        g_cursor[i] = r;
    }
    if (i == 0) g_rowptr[N_NODES] = ET;
}
__global__ void k_fill(const int* __restrict__ src, const int* __restrict__ dst) {
    int i = blockIdx.x * blockDim.x + threadIdx.x;
    if (i < N_EDGES) {
        int pos = atomicAdd(&g_cursor[dst[i]], 1);
        g_col[pos] = src[i];
    } else if (i < ET) {
        int v = i - N_EDGES;
        int pos = atomicAdd(&g_cursor[v], 1);
        g_col[pos] = v;
    }
}

// ---------------- weight split + composite vectors --------------------------
__global__ void k_padW(const float* __restrict__ W1, const float* __restrict__ W2s) {
    int i = blockIdx.x * blockDim.x + threadIdx.x;   // 65536
    int r = i >> 8, c = i & 255;
    float w1 = (c < H) ? W1[r * H + c] : 0.f;
    float w2 = (r < H && c < H) ? W2s[r * H + c] : 0.f;
    __nv_bfloat16 h1 = __float2bfloat16(w1);
    g_W1h[i] = h1;
    g_W1l[i] = __float2bfloat16(w1 - __bfloat162float(h1));
    __nv_bfloat16 h2 = __float2bfloat16(w2);
    g_W2h[i] = h2;
    g_W2l[i] = __float2bfloat16(w2 - __bfloat162float(h2));
}

__global__ void k_cvec(const float* __restrict__ W1,
                       const float* __restrict__ as1, const float* __restrict__ ad1,
                       const float* __restrict__ W2s, const float* __restrict__ W2d,
                       const float* __restrict__ as2, const float* __restrict__ ad2) {
    int t = blockIdx.x * blockDim.x + threadIdx.x;
    int vec = t >> 8, k = t & 255;
    float s = 0.f;
    if (vec == 0)      { for (int h = 0; h < H; h++) s += W1[k * H + h] * as1[h]; }
    else if (vec == 1) { for (int h = 0; h < H; h++) s += W1[k * H + h] * ad1[h]; }
    else if (vec == 2) { if (k < H) for (int h = 0; h < H; h++) s += W2s[k * H + h] * as2[h]; }
    else               { if (k < H) for (int h = 0; h < H; h++) s += W2d[k * H + h] * ad2[h]; }
    g_cv[vec][k] = s;
}

// ---------------- pack x -> bf16 hi/lo + fused layer-1 dual GEMV ------------
union U16x8 { unsigned short s[8]; uint4 q; };

__global__ void k_prepA_x(const float* __restrict__ x) {
    int gw = (blockIdx.x * blockDim.x + threadIdx.x) >> 5;
    int lane = threadIdx.x & 31;
    if (gw >= N_NODES) return;
    const float4* r = (const float4*)(x + (size_t)gw * P + lane * 8);
    float4 p0 = r[0], p1 = r[1];
    float v[8] = {p0.x, p0.y, p0.z, p0.w, p1.x, p1.y, p1.z, p1.w};
    float s1 = 0.f, s2 = 0.f;
    U16x8 hh, ll;
    #pragma unroll
    for (int e = 0; e < 8; e++) {
        int f = lane * 8 + e;
        s1 += v[e] * g_cv[0][f];
        s2 += v[e] * g_cv[1][f];
        __nv_bfloat16 hb = __float2bfloat16(v[e]);
        hh.s[e] = *(unsigned short*)&hb;
        __nv_bfloat16 lb = __float2bfloat16(v[e] - __bfloat162float(hb));
        ll.s[e] = *(unsigned short*)&lb;
    }
    size_t off = (size_t)gw * P + lane * 8;
    *(uint4*)(g_xh + off) = hh.q;
    *(uint4*)(g_xl + off) = ll.q;
    #pragma unroll
    for (int d = 16; d; d >>= 1) {
        s1 += __shfl_xor_sync(0xffffffffu, s1, d);
        s2 += __shfl_xor_sync(0xffffffffu, s2, d);
    }
    if (lane == 0) { g_as[gw] = s1; g_ad[gw] = s2; }
}

// ---------------- WMMA bf16 3-pass GEMM: C[128 rows][256] per block ---------
// smem (bf16 el): sAh[2][128*40]=10240, sAl +10240, sBh[2][32*264]=16896 @20480,
// sBl @37376. total 54272 el = 108544 B
template<int MODE>
__global__ __launch_bounds__(256, 1)
void gemm_wmma() {
    const __nv_bfloat16* Ah = MODE ? g_x1h : g_xh;
    const __nv_bfloat16* Al = MODE ? g_x1l : g_xl;
    const __nv_bfloat16* Bh = MODE ? g_W2h : g_W1h;
    const __nv_bfloat16* Bl = MODE ? g_W2l : g_W1l;
    float* C = MODE ? g_hs : g_h1;

    extern __shared__ __align__(16) unsigned char smraw[];
    __nv_bfloat16* sAh = (__nv_bfloat16*)smraw;
    __nv_bfloat16* sAl = sAh + 10240;
    __nv_bfloat16* sBh = sAh + 20480;
    __nv_bfloat16* sBl = sAh + 37376;

    int tid = threadIdx.x, wid = tid >> 5;
    int bm = blockIdx.x * 128;
    int wr = (wid >> 2) * 64, wc = (wid & 3) * 64;

    wmma::fragment<wmma::accumulator, 16, 16, 16, float> acc[4][4];
    #pragma unroll
    for (int i = 0; i < 4; i++)
        #pragma unroll
        for (int j = 0; j < 4; j++) wmma::fill_fragment(acc[i][j], 0.f);

    // stage 0 copy
    {
        #pragma unroll
        for (int l = 0; l < 2; l++) {
            int q = tid + l * 256;        // 512 uint4
            int row = q >> 2, c8 = q & 3;
            size_t g = (size_t)(bm + row) * P + c8 * 8;
            *(uint4*)(sAh + row * 40 + c8 * 8) = *(const uint4*)(Ah + g);
            *(uint4*)(sAl + row * 40 + c8 * 8) = *(const uint4*)(Al + g);
        }
        #pragma unroll
        for (int l = 0; l < 4; l++) {
            int q = tid + l * 256;        // 1024 uint4
            int row = q >> 5, c8 = q & 31;
            size_t g = (size_t)row * 256 + c8 * 8;
            *(uint4*)(sBh + row * 264 + c8 * 8) = *(const uint4*)(Bh + g);
            *(uint4*)(sBl + row * 264 + c8 * 8) = *(const uint4*)(Bl + g);
        }
    }
    __syncthreads();

    uint4 pa[2], pl[2], pbh[4], pbl[4];
    for (int it = 0; it < 8; it++) {
        int buf = it & 1, nbuf = buf ^ 1;
        if (it < 7) {
            int kt = (it + 1) * 32;
            #pragma unroll
            for (int l = 0; l < 2; l++) {
                int q = tid + l * 256;
                int row = q >> 2, c8 = q & 3;
                size_t g = (size_t)(bm + row) * P + kt + c8 * 8;
                pa[l] = *(const uint4*)(Ah + g);
                pl[l] = *(const uint4*)(Al + g);
            }
            #pragma unroll
            for (int l = 0; l < 4; l++) {
                int q = tid + l * 256;
                int row = q >> 5, c8 = q & 31;
                size_t g = (size_t)(kt + row) * 256 + c8 * 8;
                pbh[l] = *(const uint4*)(Bh + g);
                pbl[l] = *(const uint4*)(Bl + g);
            }
        }
        // compute on buf
        #pragma unroll
        for (int ks = 0; ks < 2; ks++) {
            int ko = ks * 16;
            wmma::fragment<wmma::matrix_a, 16, 16, 16, __nv_bfloat16, wmma::row_major> fah[4], fal[4];
            #pragma unroll
            for (int i = 0; i < 4; i++) {
                wmma::load_matrix_sync(fah[i], sAh + buf * 5120 + (wr + i * 16) * 40 + ko, 40);
                wmma::load_matrix_sync(fal[i], sAl + buf * 5120 + (wr + i * 16) * 40 + ko, 40);
            }
            #pragma unroll
            for (int j = 0; j < 4; j++) {
                wmma::fragment<wmma::matrix_b, 16, 16, 16, __nv_bfloat16, wmma::row_major> fbh, fbl;
                wmma::load_matrix_sync(fbh, sBh + buf * 8448 + ko * 264 + wc + j * 16, 264);
                wmma::load_matrix_sync(fbl, sBl + buf * 8448 + ko * 264 + wc + j * 16, 264);
                #pragma unroll
                for (int i = 0; i < 4; i++) {
                    wmma::mma_sync(acc[i][j], fah[i], fbh, acc[i][j]);
                    wmma::mma_sync(acc[i][j], fal[i], fbh, acc[i][j]);
                    wmma::mma_sync(acc[i][j], fah[i], fbl, acc[i][j]);
                }
            }
        }
        if (it < 7) {
            __syncthreads();
            #pragma unroll
            for (int l = 0; l < 2; l++) {
                int q = tid + l * 256;
                int row = q >> 2, c8 = q & 3;
                *(uint4*)(sAh + nbuf * 5120 + row * 40 + c8 * 8) = pa[l];
                *(uint4*)(sAl + nbuf * 5120 + row * 40 + c8 * 8) = pl[l];
            }
            #pragma unroll
            for (int l = 0; l < 4; l++) {
                int q = tid + l * 256;
                int row = q >> 5, c8 = q & 31;
                *(uint4*)(sBh + nbuf * 8448 + row * 264 + c8 * 8) = pbh[l];
                *(uint4*)(sBl + nbuf * 8448 + row * 264 + c8 * 8) = pbl[l];
            }
            __syncthreads();
        }
    }

    // guard-free full-tile epilogue (M padded to NPAD)
    #pragma unroll
    for (int i = 0; i < 4; i++)
        #pragma unroll
        for (int j = 0; j < 4; j++)
            wmma::store_matrix_sync(C + (size_t)(bm + wr + i * 16) * 256 + wc + j * 16,
                                    acc[i][j], 256, wmma::mem_row_major);
}

// ---------------- warp-per-node softmax aggregation -------------------------
// SRC 0: feats g_h1 -> x1 as bf16 hi/lo (pitch P) + fused layer-2 dots
// SRC 1: feats g_hs -> ext out (pitch H)
template<int SRC, bool RELU>
__global__ void k_agg(const float* __restrict__ bias, float* __restrict__ oext) {
    const float* hsrc = (SRC == 0) ? g_h1 : g_hs;
    const float* asv = (SRC == 0) ? g_as : g_as2;
    const float* adva = (SRC == 0) ? g_ad : g_ad2;
    int gw = (blockIdx.x * blockDim.x + threadIdx.x) >> 5;
    int lane = threadIdx.x & 31;
    if (gw >= N_NODES) return;

    int start = g_rowptr[gw], end = g_rowptr[gw + 1];
    float adv = adva[gw];

    float mx = -1e30f;
    for (int j = start + lane; j < end; j += 32)
        mx = fmaxf(mx, asv[g_col[j]]);
    #pragma unroll
    for (int d = 16; d; d >>= 1) mx = fmaxf(mx, __shfl_xor_sync(0xffffffffu, mx, d));
    float t = mx + adv;
    float m = (t > 0.f) ? t : 0.2f * t;

    float acc[8];
    #pragma unroll
    for (int k = 0; k < 8; k++) acc[k] = 0.f;
    float denom = 0.f;
    for (int j = start; j < end; j++) {
        int s = g_col[j];
        float e0 = asv[s] + adv;
        float e = (e0 > 0.f) ? e0 : 0.2f * e0;
        float w = __expf(e - m);
        denom += w;
        const float* row = hsrc + (size_t)s * P;
        #pragma unroll
        for (int k = 0; k < 8; k++)
            acc[k] += w * row[k * 32 + lane];   // cols >= H are exact zeros
    }
    float inv = 1.0f / denom;
    float s1 = 0.f, s2 = 0.f;
    #pragma unroll
    for (int k = 0; k < 8; k++) {
        int f = k * 32 + lane;
        if (f < H) {
            float v = acc[k] * inv + bias[f];
            if (RELU) v = fmaxf(v, 0.f);
            if (SRC == 0) {
                __nv_bfloat16 hb = __float2bfloat16(v);
                g_x1h[(size_t)gw * P + f] = hb;
                g_x1l[(size_t)gw * P + f] = __float2bfloat16(v - __bfloat162float(hb));
                s1 += v * g_cv[2][f];
                s2 += v * g_cv[3][f];
            } else {
                oext[(size_t)gw * H + f] = v;
            }
        }
    }
    if (SRC == 0) {
        #pragma unroll
        for (int d = 16; d; d >>= 1) {
            s1 += __shfl_xor_sync(0xffffffffu, s1, d);
            s2 += __shfl_xor_sync(0xffffffffu, s2, d);
        }
        if (lane == 0) { g_as2[gw] = s1; g_ad2[gw] = s2; }
    }
}

// ---------------- launch ----------------------------------------------------
extern "C" void kernel_launch(void* const* d_in, const int* in_sizes, int n_in,
                              void* d_out, int out_size) {
    const float* x   = (const float*)d_in[0];
    const int*   ei  = (const int*)d_in[1];
    const float* W1  = (const float*)d_in[2];
    const float* as1 = (const float*)d_in[3];
    const float* ad1 = (const float*)d_in[4];
    const float* b1  = (const float*)d_in[5];
    const float* W2s = (const float*)d_in[6];
    const float* W2d = (const float*)d_in[7];
    const float* as2 = (const float*)d_in[8];
    const float* ad2 = (const float*)d_in[9];
    const float* b2  = (const float*)d_in[10];
    float* out = (float*)d_out;

    const int* src = ei;
    const int* dst = ei + N_EDGES;

    cudaFuncSetAttribute(gemm_wmma<0>, cudaFuncAttributeMaxDynamicSharedMemorySize, SM_TOTAL);
    cudaFuncSetAttribute(gemm_wmma<1>, cudaFuncAttributeMaxDynamicSharedMemorySize, SM_TOTAL);

    int nb = (N_NODES + 1023) / 1024;

    k_init_deg<<<(N_NODES + 255) / 256, 256>>>();
    k_count<<<(N_EDGES + 255) / 256, 256>>>(dst);
    k_blockscan<<<nb, 1024>>>();
    k_partscan<<<1, 64>>>(nb);
    k_addoff<<<(N_NODES + 255) / 256, 256>>>();
    k_fill<<<(ET + 255) / 256, 256>>>(src, dst);

    k_padW<<<256, 256>>>(W1, W2s);
    k_cvec<<<4, 256>>>(W1, as1, ad1, W2s, W2d, as2, ad2);

    int warpsGrid = (N_NODES * 32 + 255) / 256;

    // layer 1
    k_prepA_x<<<warpsGrid, 256>>>(x);
    gemm_wmma<0><<<NTILES, 256, SM_TOTAL>>>();
    k_agg<0, true><<<warpsGrid, 256>>>(b1, nullptr);

    // layer 2
    gemm_wmma<1><<<NTILES, 256, SM_TOTAL>>>();
    k_agg<1, false><<<warpsGrid, 256>>>(b2, out);
}

// round 11
// speedup vs baseline: 2.7578x; 1.0067x over previous
#include <cuda_runtime.h>
#include <cuda_bf16.h>
#include <mma.h>

using namespace nvcuda;

#define N_NODES 50000
#define N_EDGES 800000
#define ET (N_EDGES + N_NODES)
#define H 250
#define P 256
#define NTILES 391
#define NPAD (NTILES * 128)
#define SM_TOTAL 108544

// ---------------- scratch (device globals; zero-initialized at load) --------
__device__ __align__(16) float g_h1[(size_t)NPAD * P];
__device__ __align__(16) float g_hs[(size_t)NPAD * P];
__device__ __align__(16) __nv_bfloat16 g_xh[(size_t)NPAD * P];
__device__ __align__(16) __nv_bfloat16 g_xl[(size_t)NPAD * P];
__device__ __align__(16) __nv_bfloat16 g_x1h[(size_t)NPAD * P];
__device__ __align__(16) __nv_bfloat16 g_x1l[(size_t)NPAD * P];
__device__ __align__(16) __nv_bfloat16 g_W1h[256 * 256], g_W1l[256 * 256];
__device__ __align__(16) __nv_bfloat16 g_W2h[256 * 256], g_W2l[256 * 256];
__device__ __align__(16) float g_cv[4][256];
__device__ float g_as[N_NODES], g_ad[N_NODES];
__device__ float g_as2[N_NODES], g_ad2[N_NODES];
__device__ int g_deg[N_NODES], g_rowptr[N_NODES + 1], g_cursor[N_NODES];
__device__ int g_col[ET];
__device__ int g_part[64];

// ---------------- CSR build -------------------------------------------------
__global__ void k_init_deg() {
    int i = blockIdx.x * blockDim.x + threadIdx.x;
    if (i < N_NODES) g_deg[i] = 1;
}
__global__ void k_count(const int* __restrict__ dst) {
    int i = blockIdx.x * blockDim.x + threadIdx.x;
    if (i < N_EDGES) atomicAdd(&g_deg[dst[i]], 1);
}
__global__ void k_blockscan() {
    __shared__ int sh[1024];
    int t = threadIdx.x, b = blockIdx.x;
    int i = b * 1024 + t;
    int v = (i < N_NODES) ? g_deg[i] : 0;
    sh[t] = v;
    __syncthreads();
    #pragma unroll
    for (int d = 1; d < 1024; d <<= 1) {
        int tv = (t >= d) ? sh[t - d] : 0;
        __syncthreads();
        sh[t] += tv;
        __syncthreads();
    }
    if (i < N_NODES) g_rowptr[i] = sh[t] - v;
    if (t == 1023) g_part[b] = sh[1023];
}
__global__ void k_partscan(int nb) {
    __shared__ int sh[64];
    int t = threadIdx.x;
    int v = (t < nb) ? g_part[t] : 0;
    sh[t] = v;
    __syncthreads();
    #pragma unroll
    for (int d = 1; d < 64; d <<= 1) {
        int tv = (t >= d) ? sh[t - d] : 0;
        __syncthreads();
        sh[t] += tv;
        __syncthreads();
    }
    if (t < nb) g_part[t] = sh[t] - v;   // exclusive
}
__global__ void k_addoff() {
    int i = blockIdx.x * blockDim.x + threadIdx.x;
    if (i < N_NODES) {
        int r = g_rowptr[i] + g_part[i >> 10];
        g_rowptr[i] = r;
        g_cursor[i] = r;
    }
    if (i == 0) g_rowptr[N_NODES] = ET;
}
__global__ void k_fill(const int* __restrict__ src, const int* __restrict__ dst) {
    int i = blockIdx.x * blockDim.x + threadIdx.x;
    if (i < N_EDGES) {
        int pos = atomicAdd(&g_cursor[dst[i]], 1);
        g_col[pos] = src[i];
    } else if (i < ET) {
        int v = i - N_EDGES;
        int pos = atomicAdd(&g_cursor[v], 1);
        g_col[pos] = v;
    }
}

// ---------------- weight split + composite vectors --------------------------
__global__ void k_padW(const float* __restrict__ W1, const float* __restrict__ W2s) {
    int i = blockIdx.x * blockDim.x + threadIdx.x;   // 65536
    int r = i >> 8, c = i & 255;
    float w1 = (c < H) ? W1[r * H + c] : 0.f;
    float w2 = (r < H && c < H) ? W2s[r * H + c] : 0.f;
    __nv_bfloat16 h1 = __float2bfloat16(w1);
    g_W1h[i] = h1;
    g_W1l[i] = __float2bfloat16(w1 - __bfloat162float(h1));
    __nv_bfloat16 h2 = __float2bfloat16(w2);
    g_W2h[i] = h2;
    g_W2l[i] = __float2bfloat16(w2 - __bfloat162float(h2));
}

__global__ void k_cvec(const float* __restrict__ W1,
                       const float* __restrict__ as1, const float* __restrict__ ad1,
                       const float* __restrict__ W2s, const float* __restrict__ W2d,
                       const float* __restrict__ as2, const float* __restrict__ ad2) {
    int t = blockIdx.x * blockDim.x + threadIdx.x;
    int vec = t >> 8, k = t & 255;
    float s = 0.f;
    if (vec == 0)      { for (int h = 0; h < H; h++) s += W1[k * H + h] * as1[h]; }
    else if (vec == 1) { for (int h = 0; h < H; h++) s += W1[k * H + h] * ad1[h]; }
    else if (vec == 2) { if (k < H) for (int h = 0; h < H; h++) s += W2s[k * H + h] * as2[h]; }
    else               { if (k < H) for (int h = 0; h < H; h++) s += W2d[k * H + h] * ad2[h]; }
    g_cv[vec][k] = s;
}

// ---------------- pack x -> bf16 hi/lo + fused layer-1 dual GEMV ------------
union U16x8 { unsigned short s[8]; uint4 q; };

__global__ void k_prepA_x(const float* __restrict__ x) {
    int gw = (blockIdx.x * blockDim.x + threadIdx.x) >> 5;
    int lane = threadIdx.x & 31;
    if (gw >= N_NODES) return;
    const float4* r = (const float4*)(x + (size_t)gw * P + lane * 8);
    float4 p0 = r[0], p1 = r[1];
    float v[8] = {p0.x, p0.y, p0.z, p0.w, p1.x, p1.y, p1.z, p1.w};
    float s1 = 0.f, s2 = 0.f;
    U16x8 hh, ll;
    #pragma unroll
    for (int e = 0; e < 8; e++) {
        int f = lane * 8 + e;
        s1 += v[e] * g_cv[0][f];
        s2 += v[e] * g_cv[1][f];
        __nv_bfloat16 hb = __float2bfloat16(v[e]);
        hh.s[e] = *(unsigned short*)&hb;
        __nv_bfloat16 lb = __float2bfloat16(v[e] - __bfloat162float(hb));
        ll.s[e] = *(unsigned short*)&lb;
    }
    size_t off = (size_t)gw * P + lane * 8;
    *(uint4*)(g_xh + off) = hh.q;
    *(uint4*)(g_xl + off) = ll.q;
    #pragma unroll
    for (int d = 16; d; d >>= 1) {
        s1 += __shfl_xor_sync(0xffffffffu, s1, d);
        s2 += __shfl_xor_sync(0xffffffffu, s2, d);
    }
    if (lane == 0) { g_as[gw] = s1; g_ad[gw] = s2; }
}

// ---------------- WMMA bf16 3-pass GEMM: C[128 rows][256] per block ---------
// smem (bf16 el): sAh[2][128*40]=10240, sAl +10240, sBh[2][32*264]=16896 @20480,
// sBl @37376. total 54272 el = 108544 B
template<int MODE>
__global__ __launch_bounds__(256, 1)
void gemm_wmma() {
    const __nv_bfloat16* Ah = MODE ? g_x1h : g_xh;
    const __nv_bfloat16* Al = MODE ? g_x1l : g_xl;
    const __nv_bfloat16* Bh = MODE ? g_W2h : g_W1h;
    const __nv_bfloat16* Bl = MODE ? g_W2l : g_W1l;
    float* C = MODE ? g_hs : g_h1;

    extern __shared__ __align__(16) unsigned char smraw[];
    __nv_bfloat16* sAh = (__nv_bfloat16*)smraw;
    __nv_bfloat16* sAl = sAh + 10240;
    __nv_bfloat16* sBh = sAh + 20480;
    __nv_bfloat16* sBl = sAh + 37376;

    int tid = threadIdx.x, wid = tid >> 5;
    int bm = blockIdx.x * 128;
    int wr = (wid >> 2) * 64, wc = (wid & 3) * 64;

    wmma::fragment<wmma::accumulator, 16, 16, 16, float> acc[4][4];
    #pragma unroll
    for (int i = 0; i < 4; i++)
        #pragma unroll
        for (int j = 0; j < 4; j++) wmma::fill_fragment(acc[i][j], 0.f);

    // stage 0 copy
    {
        #pragma unroll
        for (int l = 0; l < 2; l++) {
            int q = tid + l * 256;        // 512 uint4
            int row = q >> 2, c8 = q & 3;
            size_t g = (size_t)(bm + row) * P + c8 * 8;
            *(uint4*)(sAh + row * 40 + c8 * 8) = *(const uint4*)(Ah + g);
            *(uint4*)(sAl + row * 40 + c8 * 8) = *(const uint4*)(Al + g);
        }
        #pragma unroll
        for (int l = 0; l < 4; l++) {
            int q = tid + l * 256;        // 1024 uint4
            int row = q >> 5, c8 = q & 31;
            size_t g = (size_t)row * 256 + c8 * 8;
            *(uint4*)(sBh + row * 264 + c8 * 8) = *(const uint4*)(Bh + g);
            *(uint4*)(sBl + row * 264 + c8 * 8) = *(const uint4*)(Bl + g);
        }
    }
    __syncthreads();

    uint4 pa[2], pl[2], pbh[4], pbl[4];
    for (int it = 0; it < 8; it++) {
        int buf = it & 1, nbuf = buf ^ 1;
        if (it < 7) {
            int kt = (it + 1) * 32;
            #pragma unroll
            for (int l = 0; l < 2; l++) {
                int q = tid + l * 256;
                int row = q >> 2, c8 = q & 3;
                size_t g = (size_t)(bm + row) * P + kt + c8 * 8;
                pa[l] = *(const uint4*)(Ah + g);
                pl[l] = *(const uint4*)(Al + g);
            }
            #pragma unroll
            for (int l = 0; l < 4; l++) {
                int q = tid + l * 256;
                int row = q >> 5, c8 = q & 31;
                size_t g = (size_t)(kt + row) * 256 + c8 * 8;
                pbh[l] = *(const uint4*)(Bh + g);
                pbl[l] = *(const uint4*)(Bl + g);
            }
        }
        // compute on buf
        #pragma unroll
        for (int ks = 0; ks < 2; ks++) {
            int ko = ks * 16;
            wmma::fragment<wmma::matrix_a, 16, 16, 16, __nv_bfloat16, wmma::row_major> fah[4], fal[4];
            #pragma unroll
            for (int i = 0; i < 4; i++) {
                wmma::load_matrix_sync(fah[i], sAh + buf * 5120 + (wr + i * 16) * 40 + ko, 40);
                wmma::load_matrix_sync(fal[i], sAl + buf * 5120 + (wr + i * 16) * 40 + ko, 40);
            }
            #pragma unroll
            for (int j = 0; j < 4; j++) {
                wmma::fragment<wmma::matrix_b, 16, 16, 16, __nv_bfloat16, wmma::row_major> fbh, fbl;
                wmma::load_matrix_sync(fbh, sBh + buf * 8448 + ko * 264 + wc + j * 16, 264);
                wmma::load_matrix_sync(fbl, sBl + buf * 8448 + ko * 264 + wc + j * 16, 264);
                #pragma unroll
                for (int i = 0; i < 4; i++) {
                    wmma::mma_sync(acc[i][j], fah[i], fbh, acc[i][j]);
                    wmma::mma_sync(acc[i][j], fal[i], fbh, acc[i][j]);
                    wmma::mma_sync(acc[i][j], fah[i], fbl, acc[i][j]);
                }
            }
        }
        if (it < 7) {
            __syncthreads();
            #pragma unroll
            for (int l = 0; l < 2; l++) {
                int q = tid + l * 256;
                int row = q >> 2, c8 = q & 3;
                *(uint4*)(sAh + nbuf * 5120 + row * 40 + c8 * 8) = pa[l];
                *(uint4*)(sAl + nbuf * 5120 + row * 40 + c8 * 8) = pl[l];
            }
            #pragma unroll
            for (int l = 0; l < 4; l++) {
                int q = tid + l * 256;
                int row = q >> 5, c8 = q & 31;
                *(uint4*)(sBh + nbuf * 8448 + row * 264 + c8 * 8) = pbh[l];
                *(uint4*)(sBl + nbuf * 8448 + row * 264 + c8 * 8) = pbl[l];
            }
            __syncthreads();
        }
    }

    // guard-free full-tile epilogue (M padded to NPAD)
    #pragma unroll
    for (int i = 0; i < 4; i++)
        #pragma unroll
        for (int j = 0; j < 4; j++)
            wmma::store_matrix_sync(C + (size_t)(bm + wr + i * 16) * 256 + wc + j * 16,
                                    acc[i][j], 256, wmma::mem_row_major);
}

// ---------------- warp-per-node softmax aggregation -------------------------
// SRC 0: feats g_h1 -> x1 as bf16 hi/lo (pitch P) + fused layer-2 dots
// SRC 1: feats g_hs -> ext out (pitch H)
template<int SRC, bool RELU>
__global__ void k_agg(const float* __restrict__ bias, float* __restrict__ oext) {
    const float* hsrc = (SRC == 0) ? g_h1 : g_hs;
    const float* asv = (SRC == 0) ? g_as : g_as2;
    const float* adva = (SRC == 0) ? g_ad : g_ad2;
    int gw = (blockIdx.x * blockDim.x + threadIdx.x) >> 5;
    int lane = threadIdx.x & 31;
    if (gw >= N_NODES) return;

    int start = g_rowptr[gw], end = g_rowptr[gw + 1];
    float adv = adva[gw];

    float mx = -1e30f;
    for (int j = start + lane; j < end; j += 32)
        mx = fmaxf(mx, asv[g_col[j]]);
    #pragma unroll
    for (int d = 16; d; d >>= 1) mx = fmaxf(mx, __shfl_xor_sync(0xffffffffu, mx, d));
    float t = mx + adv;
    float m = (t > 0.f) ? t : 0.2f * t;

    float acc[8];
    #pragma unroll
    for (int k = 0; k < 8; k++) acc[k] = 0.f;
    float denom = 0.f;
    for (int j = start; j < end; j++) {
        int s = g_col[j];
        float e0 = asv[s] + adv;
        float e = (e0 > 0.f) ? e0 : 0.2f * e0;
        float w = __expf(e - m);
        denom += w;
        const float* row = hsrc + (size_t)s * P;
        #pragma unroll
        for (int k = 0; k < 8; k++)
            acc[k] += w * row[k * 32 + lane];   // cols >= H are exact zeros
    }
    float inv = 1.0f / denom;
    float s1 = 0.f, s2 = 0.f;
    #pragma unroll
    for (int k = 0; k < 8; k++) {
        int f = k * 32 + lane;
        if (f < H) {
            float v = acc[k] * inv + bias[f];
            if (RELU) v = fmaxf(v, 0.f);
            if (SRC == 0) {
                __nv_bfloat16 hb = __float2bfloat16(v);
                g_x1h[(size_t)gw * P + f] = hb;
                g_x1l[(size_t)gw * P + f] = __float2bfloat16(v - __bfloat162float(hb));
                s1 += v * g_cv[2][f];
                s2 += v * g_cv[3][f];
            } else {
                oext[(size_t)gw * H + f] = v;
            }
        }
    }
    if (SRC == 0) {
        #pragma unroll
        for (int d = 16; d; d >>= 1) {
            s1 += __shfl_xor_sync(0xffffffffu, s1, d);
            s2 += __shfl_xor_sync(0xffffffffu, s2, d);
        }
        if (lane == 0) { g_as2[gw] = s1; g_ad2[gw] = s2; }
    }
}

// ---------------- launch ----------------------------------------------------
extern "C" void kernel_launch(void* const* d_in, const int* in_sizes, int n_in,
                              void* d_out, int out_size) {
    const float* x   = (const float*)d_in[0];
    const int*   ei  = (const int*)d_in[1];
    const float* W1  = (const float*)d_in[2];
    const float* as1 = (const float*)d_in[3];
    const float* ad1 = (const float*)d_in[4];
    const float* b1  = (const float*)d_in[5];
    const float* W2s = (const float*)d_in[6];
    const float* W2d = (const float*)d_in[7];
    const float* as2 = (const float*)d_in[8];
    const float* ad2 = (const float*)d_in[9];
    const float* b2  = (const float*)d_in[10];
    float* out = (float*)d_out;

    const int* src = ei;
    const int* dst = ei + N_EDGES;

    cudaFuncSetAttribute(gemm_wmma<0>, cudaFuncAttributeMaxDynamicSharedMemorySize, SM_TOTAL);
    cudaFuncSetAttribute(gemm_wmma<1>, cudaFuncAttributeMaxDynamicSharedMemorySize, SM_TOTAL);

    int nb = (N_NODES + 1023) / 1024;

    k_init_deg<<<(N_NODES + 255) / 256, 256>>>();
    k_count<<<(N_EDGES + 255) / 256, 256>>>(dst);
    k_blockscan<<<nb, 1024>>>();
    k_partscan<<<1, 64>>>(nb);
    k_addoff<<<(N_NODES + 255) / 256, 256>>>();
    k_fill<<<(ET + 255) / 256, 256>>>(src, dst);

    k_padW<<<256, 256>>>(W1, W2s);
    k_cvec<<<4, 256>>>(W1, as1, ad1, W2s, W2d, as2, ad2);

    int warpsGrid = (N_NODES * 32 + 255) / 256;

    // layer 1
    k_prepA_x<<<warpsGrid, 256>>>(x);
    gemm_wmma<0><<<NTILES, 256, SM_TOTAL>>>();
    k_agg<0, true><<<warpsGrid, 256>>>(b1, nullptr);

    // layer 2
    gemm_wmma<1><<<NTILES, 256, SM_TOTAL>>>();
    k_agg<1, false><<<warpsGrid, 256>>>(b2, out);
}